// round 10
// baseline (speedup 1.0000x reference)
#include <cuda_runtime.h>
#include <cuda_bf16.h>
#include <cooperative_groups.h>

namespace cg = cooperative_groups;

// ---------------------------------------------------------------------------
// Fused persistent kernel: 128 blocks = 32 clusters of 4, TWO grid syncs.
// Only feat[0:64] is live -> 500K-row MLP collapses to 64 rows.
// KEY ALGEBRA: agg = mean_g(y_g) = (mean_g ts_g) @ Wn2 + bn2  (y is linear in
// ts), so the per-row y layer (and per-block Wn2 reads) is eliminated.
//
// Phase 1 (all 128 blocks; cluster cid=b>>2 owns rows 2cid,2cid+1; rank
//   q=b&3 owns col quarter): winner -> MLP (L3 quarter) -> DSMEM gf gather ->
//   ts quarter = relu(gf@Wn1[:,quarter]+bn1) -> g_ts.       [128 KB/block]
// gsync
// Phase 2 (blocks 0-15, c-slice s=b of 16 cols):
//   tbar = mean_g g_ts (full, redundant) ; agg_s = tbar@Wn2[:,s]+bn2[s] ;
//   pz[s][k][d] = sum_{c in s} agg_s[c]*Wh1[k][c][d] -> g_pz. [~84 KB/block]
// gsync
// Phase 3 (blocks 0-3, head k=b): z = sum_s pz[s][k] (fixed order) + bh1,
//   relu, dot Wh2 (shfl tree, fixed assoc) -> out[k].        [~8 KB]
// ---------------------------------------------------------------------------

#define G   64
#define NB  128

__device__ float g_ts[G * 256];
__device__ float g_pz[16 * 4 * 128];
__device__ unsigned long long g_ctr;   // monotonic across launches/replays

__device__ __forceinline__ void gsync()
{
    __syncthreads();
    if (threadIdx.x == 0) {
        __threadfence();
        unsigned long long ticket = atomicAdd(&g_ctr, 1ULL) + 1ULL;
        unsigned long long target = ((ticket + (NB - 1)) / NB) * (unsigned long long)NB;
        volatile unsigned long long* p = (volatile unsigned long long*)&g_ctr;
        while (*p < target) { }
        __threadfence();
    }
    __syncthreads();
}

struct SmemLayout {
    float  gf[2 * 256];     // gf rows (phase1) / tbar (phase2)
    float4 sp4[512];        // chunk partials
    float  ps[192];
    float  gs[192];
    float  h1[2 * 64];      // h1 rows (phase1) / agg slice (phase2)
    float  h2[2 * 128];
    float  p[8];
    int    si[G];
    int    sw[4];
};

__global__ void __launch_bounds__(256, 1) __cluster_dims__(4, 1, 1)
fused_kernel(const float* __restrict__ pos, const float* __restrict__ gp,
             const float* __restrict__ W1,  const float* __restrict__ b1,
             const float* __restrict__ W2,  const float* __restrict__ b2,
             const float* __restrict__ W3,  const float* __restrict__ b3,
             const float* __restrict__ Wn1, const float* __restrict__ bn1,
             const float* __restrict__ Wn2, const float* __restrict__ bn2,
             const float* __restrict__ Wh1, const float* __restrict__ bh1,
             const float* __restrict__ Wh2, const float* __restrict__ bh2,
             float* __restrict__ out)
{
    __shared__ SmemLayout sm;
    const int b = blockIdx.x;
    const int t = threadIdx.x;
    cg::cluster_group cluster = cg::this_cluster();
    const int q   = b & 3;             // column quarter rank
    const int cid = b >> 2;
    const int r0  = cid * 2;
    const int r1  = r0 + 1;

    // ================= Phase 1 =================
    // ---- winner table (redundant per block) ----
    if (t < G * 3) { sm.ps[t] = pos[t]; sm.gs[t] = gp[t]; }
    __syncthreads();
    if (t < G) {
        const float px = sm.ps[t * 3], py = sm.ps[t * 3 + 1], pz = sm.ps[t * 3 + 2];
        float best = 3.4e38f; int bj = 0;
        #pragma unroll 4
        for (int j = 0; j < G; j++) {
            float dx = px - sm.gs[j * 3];
            float dy = py - sm.gs[j * 3 + 1];
            float dz = pz - sm.gs[j * 3 + 2];
            float d  = dx * dx + dy * dy + dz * dz;
            if (d < best) { best = d; bj = j; }     // argmin: first idx on ties
        }
        sm.si[t] = bj;
    }
    __syncthreads();
    if (t < G) {
        int c0 = (sm.si[t] == r0) ? t : -1;
        int c1 = (sm.si[t] == r1) ? t : -1;
        #pragma unroll
        for (int off = 16; off; off >>= 1) {
            c0 = max(c0, __shfl_xor_sync(0xffffffffu, c0, off));
            c1 = max(c1, __shfl_xor_sync(0xffffffffu, c1, off));
        }
        if ((t & 31) == 0) { sm.sw[t >> 5] = c0; sm.sw[2 + (t >> 5)] = c1; }
    }
    __syncthreads();
    const int w0 = max(sm.sw[0], sm.sw[1]);
    const int w1 = max(sm.sw[2], sm.sw[3]);

    // ---- MLP for both rows (clip(winner,0); zero-mask at gf) ----
    if (t < 3) {
        sm.p[t]     = pos[max(w0, 0) * 3 + t];
        sm.p[4 + t] = pos[max(w1, 0) * 3 + t];
    }
    __syncthreads();
    if (t < 64) {       // layer1: 3 -> 64, both rows
        float wa = W1[t], wb = W1[64 + t], wc = W1[128 + t], bb = b1[t];
        sm.h1[t]      = fmaxf(bb + sm.p[0] * wa + sm.p[1] * wb + sm.p[2] * wc, 0.0f);
        sm.h1[64 + t] = fmaxf(bb + sm.p[4] * wa + sm.p[5] * wb + sm.p[6] * wc, 0.0f);
    }
    __syncthreads();
    {   // layer2: 64 -> 128, both rows; 32 float4 col-groups, 8 chunks x 8 k
        const float4* W = (const float4*)W2;        // [64][32]
        const int c  = t & 31;
        const int ch = t >> 5;
        float4 a0 = {0,0,0,0}, a1 = {0,0,0,0};
        #pragma unroll
        for (int j = 0; j < 8; j++) {
            int k = ch * 8 + j;
            float4 wv = W[k * 32 + c];
            float  x0 = sm.h1[k], x1 = sm.h1[64 + k];
            a0.x = fmaf(x0, wv.x, a0.x); a0.y = fmaf(x0, wv.y, a0.y);
            a0.z = fmaf(x0, wv.z, a0.z); a0.w = fmaf(x0, wv.w, a0.w);
            a1.x = fmaf(x1, wv.x, a1.x); a1.y = fmaf(x1, wv.y, a1.y);
            a1.z = fmaf(x1, wv.z, a1.z); a1.w = fmaf(x1, wv.w, a1.w);
        }
        sm.sp4[ch * 32 + c]       = a0;
        sm.sp4[256 + ch * 32 + c] = a1;
    }
    __syncthreads();
    if (t < 64) {       // combine layer2
        const int row = t >> 5;
        const int c   = t & 31;
        float4 a = sm.sp4[row * 256 + c];
        #pragma unroll
        for (int s = 1; s < 8; s++) {
            float4 v = sm.sp4[row * 256 + s * 32 + c];
            a.x += v.x; a.y += v.y; a.z += v.z; a.w += v.w;
        }
        const int o = c * 4;
        float4 bb = *(const float4*)(b2 + o);
        float* dst = sm.h2 + row * 128 + o;
        dst[0] = fmaxf(a.x + bb.x, 0.0f);
        dst[1] = fmaxf(a.y + bb.y, 0.0f);
        dst[2] = fmaxf(a.z + bb.z, 0.0f);
        dst[3] = fmaxf(a.w + bb.w, 0.0f);
    }
    __syncthreads();
    {   // layer3 QUARTER: 64 cols of gf, both rows; 16 groups, 16 chunks x 8 k
        const float4* W = (const float4*)W3;        // [128][64]
        const int c  = t & 15;
        const int ch = t >> 4;
        float4 a0 = {0,0,0,0}, a1 = {0,0,0,0};
        #pragma unroll
        for (int j = 0; j < 8; j++) {
            int k = ch * 8 + j;
            float4 wv = W[k * 64 + q * 16 + c];
            float  x0 = sm.h2[k], x1 = sm.h2[128 + k];
            a0.x = fmaf(x0, wv.x, a0.x); a0.y = fmaf(x0, wv.y, a0.y);
            a0.z = fmaf(x0, wv.z, a0.z); a0.w = fmaf(x0, wv.w, a0.w);
            a1.x = fmaf(x1, wv.x, a1.x); a1.y = fmaf(x1, wv.y, a1.y);
            a1.z = fmaf(x1, wv.z, a1.z); a1.w = fmaf(x1, wv.w, a1.w);
        }
        sm.sp4[ch * 16 + c]       = a0;
        sm.sp4[256 + ch * 16 + c] = a1;
    }
    __syncthreads();
    if (t < 32) {       // combine gf quarter
        const int row = t >> 4;
        const int c   = t & 15;
        float4 a = sm.sp4[row * 256 + c];
        #pragma unroll
        for (int s = 1; s < 16; s++) {
            float4 v = sm.sp4[row * 256 + s * 16 + c];
            a.x += v.x; a.y += v.y; a.z += v.z; a.w += v.w;
        }
        const int o = q * 64 + c * 4;
        float4 bb = *(const float4*)(b3 + o);
        const int wr = row ? w1 : w0;
        const float m = (wr >= 0) ? 1.0f : 0.0f;
        float* dst = sm.gf + row * 256 + o;
        dst[0] = (a.x + bb.x) * m;
        dst[1] = (a.y + bb.y) * m;
        dst[2] = (a.z + bb.z) * m;
        dst[3] = (a.w + bb.w) * m;
    }
    __syncthreads();

    // ---- all-gather gf quarters via DSMEM ----
    cluster.sync();
    if (t < 96) {
        const int pid = t >> 5;                     // 0..2 peer slot
        const int qp  = pid + (pid >= q ? 1 : 0);
        const int idx = t & 31;
        const int row = idx >> 4;
        const int c   = idx & 15;
        const float* peer_gf = cluster.map_shared_rank((const float*)sm.gf, qp);
        const int o = row * 256 + qp * 64 + c * 4;
        *(float4*)(sm.gf + o) = *(const float4*)(peer_gf + o);
    }
    __syncthreads();

    // ---- ts quarter: relu(gf @ Wn1[:,quarter] + bn1) -> g_ts, both rows ----
    {
        const float4* W = (const float4*)Wn1;       // [256][64]
        const int c  = t & 15;
        const int ch = t >> 4;                      // 16 chunks x 16 k
        float4 a0 = {0,0,0,0}, a1 = {0,0,0,0};
        #pragma unroll
        for (int j = 0; j < 16; j++) {
            int k = ch * 16 + j;
            float4 wv = W[k * 64 + q * 16 + c];
            float  x0 = sm.gf[k], x1 = sm.gf[256 + k];
            a0.x = fmaf(x0, wv.x, a0.x); a0.y = fmaf(x0, wv.y, a0.y);
            a0.z = fmaf(x0, wv.z, a0.z); a0.w = fmaf(x0, wv.w, a0.w);
            a1.x = fmaf(x1, wv.x, a1.x); a1.y = fmaf(x1, wv.y, a1.y);
            a1.z = fmaf(x1, wv.z, a1.z); a1.w = fmaf(x1, wv.w, a1.w);
        }
        sm.sp4[ch * 16 + c]       = a0;
        sm.sp4[256 + ch * 16 + c] = a1;
    }
    __syncthreads();
    if (t < 32) {
        const int row = t >> 4;
        const int c   = t & 15;
        float4 a = sm.sp4[row * 256 + c];
        #pragma unroll
        for (int s = 1; s < 16; s++) {
            float4 v = sm.sp4[row * 256 + s * 16 + c];
            a.x += v.x; a.y += v.y; a.z += v.z; a.w += v.w;
        }
        const int o = q * 64 + c * 4;
        float4 bb = *(const float4*)(bn1 + o);
        const int r = row ? r1 : r0;
        float4 v;
        v.x = fmaxf(a.x + bb.x, 0.0f);
        v.y = fmaxf(a.y + bb.y, 0.0f);
        v.z = fmaxf(a.z + bb.z, 0.0f);
        v.w = fmaxf(a.w + bb.w, 0.0f);
        *(float4*)(g_ts + r * 256 + o) = v;
    }

    gsync();

    // ======== Phase 2: blocks 0-15, c-slice s = b (16 cols) ========
    if (b < 16) {
        float* tb   = sm.gf;                        // tbar[256]
        float* aggs = sm.h1;                        // agg slice [16]

        {   // tbar = mean over 64 rows of g_ts (4 row-chunks x 16, fixed order)
            const float4* T = (const float4*)g_ts;  // [64][64]
            const int cg = t & 63, rc = t >> 6;
            float4 a = {0,0,0,0};
            #pragma unroll
            for (int j = 0; j < 16; j++) {
                const float4 v = T[(rc * 16 + j) * 64 + cg];
                a.x += v.x; a.y += v.y; a.z += v.z; a.w += v.w;
            }
            sm.sp4[rc * 64 + cg] = a;
        }
        __syncthreads();
        if (t < 64) {
            float4 a = sm.sp4[t];
            #pragma unroll
            for (int s = 1; s < 4; s++) {
                const float4 v = sm.sp4[s * 64 + t];
                a.x += v.x; a.y += v.y; a.z += v.z; a.w += v.w;
            }
            a.x *= (1.0f / 64.0f); a.y *= (1.0f / 64.0f);
            a.z *= (1.0f / 64.0f); a.w *= (1.0f / 64.0f);
            ((float4*)tb)[t] = a;
        }
        __syncthreads();

        {   // agg_s = tbar @ Wn2[:, slice] + bn2[slice]  (64 j-slices x 4 j)
            const float4* W = (const float4*)Wn2;   // [256][64]
            const int g2 = t & 3, cs = t >> 2;
            float4 acc = {0,0,0,0};
            #pragma unroll
            for (int j2 = 0; j2 < 4; j2++) {
                const int j = cs * 4 + j2;
                const float4 wv = W[j * 64 + b * 4 + g2];
                const float  x  = tb[j];
                acc.x = fmaf(x, wv.x, acc.x); acc.y = fmaf(x, wv.y, acc.y);
                acc.z = fmaf(x, wv.z, acc.z); acc.w = fmaf(x, wv.w, acc.w);
            }
            sm.sp4[cs * 4 + g2] = acc;
        }
        __syncthreads();
        if (t < 4) {
            float4 a = sm.sp4[t];
            for (int s = 1; s < 64; s++) {          // fixed ascending order
                const float4 v = sm.sp4[s * 4 + t];
                a.x += v.x; a.y += v.y; a.z += v.z; a.w += v.w;
            }
            const float4 bb = *(const float4*)(bn2 + b * 16 + t * 4);
            aggs[t * 4 + 0] = a.x + bb.x;
            aggs[t * 4 + 1] = a.y + bb.y;
            aggs[t * 4 + 2] = a.z + bb.z;
            aggs[t * 4 + 3] = a.w + bb.w;
        }
        __syncthreads();

        {   // pz[s][k][d] = sum_{c in slice} aggs[c] * Wh1[k][slice_c][d]
            const int dg = t & 31;                  // 32 float4 d-groups
            const int kk = (t >> 5) & 3;            // head
            const int hf = t >> 7;                  // c-half of slice (2 x 8)
            const float* Wb = Wh1 + kk * 32768 + (b * 16 + hf * 8) * 128 + dg * 4;
            float4 acc = {0,0,0,0};
            #pragma unroll
            for (int c2 = 0; c2 < 8; c2++) {
                const float  av = aggs[hf * 8 + c2];
                const float4 wv = *(const float4*)(Wb + c2 * 128);
                acc.x = fmaf(av, wv.x, acc.x); acc.y = fmaf(av, wv.y, acc.y);
                acc.z = fmaf(av, wv.z, acc.z); acc.w = fmaf(av, wv.w, acc.w);
            }
            sm.sp4[hf * 128 + (kk * 32 + dg)] = acc;
        }
        __syncthreads();
        if (t < 128) {
            float4 a = sm.sp4[t];
            const float4 v = sm.sp4[128 + t];
            a.x += v.x; a.y += v.y; a.z += v.z; a.w += v.w;
            *(float4*)(g_pz + b * 512 + t * 4) = a;
        }
    }

    gsync();

    // ======== Phase 3: blocks 0-3, head k = b ========
    if (b < 4 && t < 32) {
        float4 z = {0,0,0,0};
        #pragma unroll
        for (int s = 0; s < 16; s++) {              // fixed ascending order
            const float4 v = *(const float4*)(g_pz + s * 512 + b * 128 + t * 4);
            z.x += v.x; z.y += v.y; z.z += v.z; z.w += v.w;
        }
        const float4 bb = *(const float4*)(bh1 + b * 128 + t * 4);
        float4 h;
        h.x = fmaxf(z.x + bb.x, 0.0f);
        h.y = fmaxf(z.y + bb.y, 0.0f);
        h.z = fmaxf(z.z + bb.z, 0.0f);
        h.w = fmaxf(z.w + bb.w, 0.0f);
        const float4 wv = *(const float4*)(Wh2 + b * 128 + t * 4);
        float p2 = h.x * wv.x + h.y * wv.y + h.z * wv.z + h.w * wv.w;
        #pragma unroll
        for (int off = 16; off; off >>= 1)
            p2 += __shfl_xor_sync(0xffffffffu, p2, off);
        if (t == 0) out[b] = p2 + bh2[b];
    }
}

extern "C" void kernel_launch(void* const* d_in, const int* in_sizes, int n_in,
                              void* d_out, int out_size)
{
    const float* positions = (const float*)d_in[0];
    const float* grid_pts  = (const float*)d_in[1];
    const float* W1  = (const float*)d_in[2];
    const float* b1  = (const float*)d_in[3];
    const float* W2  = (const float*)d_in[4];
    const float* b2  = (const float*)d_in[5];
    const float* W3  = (const float*)d_in[6];
    const float* b3  = (const float*)d_in[7];
    const float* Wn1 = (const float*)d_in[8];
    const float* bn1 = (const float*)d_in[9];
    const float* Wn2 = (const float*)d_in[10];
    const float* bn2 = (const float*)d_in[11];
    const float* Wh1 = (const float*)d_in[12];
    const float* bh1 = (const float*)d_in[13];
    const float* Wh2 = (const float*)d_in[14];
    const float* bh2 = (const float*)d_in[15];
    float* out = (float*)d_out;

    fused_kernel<<<NB, 256>>>(positions, grid_pts, W1, b1, W2, b2, W3, b3,
                              Wn1, bn1, Wn2, bn2, Wh1, bh1, Wh2, bh2, out);
}

// round 11
// speedup vs baseline: 1.0151x; 1.0151x over previous
#include <cuda_runtime.h>
#include <cuda_bf16.h>
#include <cooperative_groups.h>

namespace cg = cooperative_groups;

// ---------------------------------------------------------------------------
// Fused persistent kernel: 64 blocks = 16 clusters of 4, ONE grid sync.
// Only feat[0:64] is live (winner in -1..63) -> 500K-row MLP collapses to 64.
//
// Cluster cid = b>>2 owns rows 4cid..4cid+3; rank q = b&3 owns column
// quarter [64q, 64q+64) of every 256-wide activation (R6 structure, 4 rows):
//   winner table redundant -> MLP (L3 quarter) -> DSMEM gf gather ->
//   ts quarter -> DSMEM ts gather -> y quarter -> g_y.
// gsync (64 blocks)
//   blocks 0-3: agg = mean(g_y); head k=b -> out[k]   (R6 tail verbatim)
// Per-block weights: 192 KB (same as R6); chip L2 traffic halved; gsync
// participants halved.
// ---------------------------------------------------------------------------

#define G   64
#define NB  64

__device__ float g_y[G * 256];
__device__ unsigned long long g_ctr;   // monotonic across launches/replays

__device__ __forceinline__ void gsync()
{
    __syncthreads();
    if (threadIdx.x == 0) {
        __threadfence();
        unsigned long long ticket = atomicAdd(&g_ctr, 1ULL) + 1ULL;
        unsigned long long target = ((ticket + (NB - 1)) / NB) * (unsigned long long)NB;
        volatile unsigned long long* p = (volatile unsigned long long*)&g_ctr;
        while (*p < target) { }
        __threadfence();
    }
    __syncthreads();
}

struct SmemLayout {
    float4 sp4[1024];       // chunk partials (16 KB)
    float  gf[4 * 256];     // 4 full gf rows
    float  ts[4 * 256];     // 4 full ts rows (reused as agg in heads)
    float  h2[4 * 128];
    float  h1[4 * 64];
    float  ps[192];
    float  gs[192];
    float  p[16];
    float  h1s[128];
    int    si[G];
    int    sw[8];
    int    swf[4];
};

__global__ void __launch_bounds__(256, 1) __cluster_dims__(4, 1, 1)
fused_kernel(const float* __restrict__ pos, const float* __restrict__ gp,
             const float* __restrict__ W1,  const float* __restrict__ b1,
             const float* __restrict__ W2,  const float* __restrict__ b2,
             const float* __restrict__ W3,  const float* __restrict__ b3,
             const float* __restrict__ Wn1, const float* __restrict__ bn1,
             const float* __restrict__ Wn2, const float* __restrict__ bn2,
             const float* __restrict__ Wh1, const float* __restrict__ bh1,
             const float* __restrict__ Wh2, const float* __restrict__ bh2,
             float* __restrict__ out)
{
    __shared__ SmemLayout sm;
    const int b = blockIdx.x;
    const int t = threadIdx.x;
    cg::cluster_group cluster = cg::this_cluster();
    const int q      = b & 3;          // column quarter rank
    const int cid    = b >> 2;
    const int r_base = cid * 4;        // 4 rows per cluster

    // ---- winner table (redundant per block) ----
    if (t < G * 3) { sm.ps[t] = pos[t]; sm.gs[t] = gp[t]; }
    __syncthreads();
    if (t < G) {
        const float px = sm.ps[t * 3], py = sm.ps[t * 3 + 1], pz = sm.ps[t * 3 + 2];
        float best = 3.4e38f; int bj = 0;
        #pragma unroll 4
        for (int j = 0; j < G; j++) {
            float dx = px - sm.gs[j * 3];
            float dy = py - sm.gs[j * 3 + 1];
            float dz = pz - sm.gs[j * 3 + 2];
            float d  = dx * dx + dy * dy + dz * dz;
            if (d < best) { best = d; bj = j; }     // argmin: first idx on ties
        }
        sm.si[t] = bj;
    }
    __syncthreads();
    if (t < G) {
        #pragma unroll
        for (int row = 0; row < 4; row++) {
            int cand = (sm.si[t] == r_base + row) ? t : -1;
            #pragma unroll
            for (int off = 16; off; off >>= 1)
                cand = max(cand, __shfl_xor_sync(0xffffffffu, cand, off));
            if ((t & 31) == 0) sm.sw[row * 2 + (t >> 5)] = cand;
        }
    }
    __syncthreads();
    if (t < 4) sm.swf[t] = max(sm.sw[t * 2], sm.sw[t * 2 + 1]);
    __syncthreads();

    // ---- MLP L1 (3->64), 4 rows (clip(winner,0); zero-mask at gf) ----
    if (t < 16) {
        const int row = t >> 2, comp = t & 3;
        if (comp < 3) sm.p[row * 4 + comp] = pos[max(sm.swf[row], 0) * 3 + comp];
    }
    __syncthreads();
    if (t < 64) {
        const float wa = W1[t], wb = W1[64 + t], wc = W1[128 + t], bb = b1[t];
        #pragma unroll
        for (int row = 0; row < 4; row++) {
            float a = bb + sm.p[row * 4] * wa + sm.p[row * 4 + 1] * wb + sm.p[row * 4 + 2] * wc;
            sm.h1[row * 64 + t] = fmaxf(a, 0.0f);
        }
    }
    __syncthreads();

    // ---- MLP L2 (64->128), 4 rows, full W2 (32 KB) ----
    {
        const float4* W = (const float4*)W2;        // [64][32]
        const int c  = t & 31;
        const int ch = t >> 5;                      // 8 chunks x 8 k
        float4 a0 = {0,0,0,0}, a1 = {0,0,0,0}, a2 = {0,0,0,0}, a3 = {0,0,0,0};
        #pragma unroll
        for (int j = 0; j < 8; j++) {
            const int k = ch * 8 + j;
            const float4 wv = W[k * 32 + c];
            const float x0 = sm.h1[k], x1 = sm.h1[64 + k], x2 = sm.h1[128 + k], x3 = sm.h1[192 + k];
            a0.x = fmaf(x0, wv.x, a0.x); a0.y = fmaf(x0, wv.y, a0.y); a0.z = fmaf(x0, wv.z, a0.z); a0.w = fmaf(x0, wv.w, a0.w);
            a1.x = fmaf(x1, wv.x, a1.x); a1.y = fmaf(x1, wv.y, a1.y); a1.z = fmaf(x1, wv.z, a1.z); a1.w = fmaf(x1, wv.w, a1.w);
            a2.x = fmaf(x2, wv.x, a2.x); a2.y = fmaf(x2, wv.y, a2.y); a2.z = fmaf(x2, wv.z, a2.z); a2.w = fmaf(x2, wv.w, a2.w);
            a3.x = fmaf(x3, wv.x, a3.x); a3.y = fmaf(x3, wv.y, a3.y); a3.z = fmaf(x3, wv.z, a3.z); a3.w = fmaf(x3, wv.w, a3.w);
        }
        sm.sp4[0 * 256 + ch * 32 + c] = a0;
        sm.sp4[1 * 256 + ch * 32 + c] = a1;
        sm.sp4[2 * 256 + ch * 32 + c] = a2;
        sm.sp4[3 * 256 + ch * 32 + c] = a3;
    }
    __syncthreads();
    if (t < 128) {
        const int row = t >> 5, c = t & 31;
        float4 a = sm.sp4[row * 256 + c];
        #pragma unroll
        for (int s = 1; s < 8; s++) {
            const float4 v = sm.sp4[row * 256 + s * 32 + c];
            a.x += v.x; a.y += v.y; a.z += v.z; a.w += v.w;
        }
        const float4 bb = *(const float4*)(b2 + c * 4);
        float* dst = sm.h2 + row * 128 + c * 4;
        dst[0] = fmaxf(a.x + bb.x, 0.0f);
        dst[1] = fmaxf(a.y + bb.y, 0.0f);
        dst[2] = fmaxf(a.z + bb.z, 0.0f);
        dst[3] = fmaxf(a.w + bb.w, 0.0f);
    }
    __syncthreads();

    // ---- MLP L3 QUARTER (128 -> 64 cols), 4 rows (W3/4 = 32 KB) ----
    {
        const float4* W = (const float4*)W3;        // [128][64]
        const int c  = t & 15;
        const int ch = t >> 4;                      // 16 chunks x 8 k
        float4 a0 = {0,0,0,0}, a1 = {0,0,0,0}, a2 = {0,0,0,0}, a3 = {0,0,0,0};
        #pragma unroll
        for (int j = 0; j < 8; j++) {
            const int k = ch * 8 + j;
            const float4 wv = W[k * 64 + q * 16 + c];
            const float x0 = sm.h2[k], x1 = sm.h2[128 + k], x2 = sm.h2[256 + k], x3 = sm.h2[384 + k];
            a0.x = fmaf(x0, wv.x, a0.x); a0.y = fmaf(x0, wv.y, a0.y); a0.z = fmaf(x0, wv.z, a0.z); a0.w = fmaf(x0, wv.w, a0.w);
            a1.x = fmaf(x1, wv.x, a1.x); a1.y = fmaf(x1, wv.y, a1.y); a1.z = fmaf(x1, wv.z, a1.z); a1.w = fmaf(x1, wv.w, a1.w);
            a2.x = fmaf(x2, wv.x, a2.x); a2.y = fmaf(x2, wv.y, a2.y); a2.z = fmaf(x2, wv.z, a2.z); a2.w = fmaf(x2, wv.w, a2.w);
            a3.x = fmaf(x3, wv.x, a3.x); a3.y = fmaf(x3, wv.y, a3.y); a3.z = fmaf(x3, wv.z, a3.z); a3.w = fmaf(x3, wv.w, a3.w);
        }
        sm.sp4[0 * 256 + ch * 16 + c] = a0;
        sm.sp4[1 * 256 + ch * 16 + c] = a1;
        sm.sp4[2 * 256 + ch * 16 + c] = a2;
        sm.sp4[3 * 256 + ch * 16 + c] = a3;
    }
    __syncthreads();
    if (t < 64) {       // combine gf quarter: 4 rows x 16 groups
        const int row = t >> 4, c = t & 15;
        float4 a = sm.sp4[row * 256 + c];
        #pragma unroll
        for (int s = 1; s < 16; s++) {
            const float4 v = sm.sp4[row * 256 + s * 16 + c];
            a.x += v.x; a.y += v.y; a.z += v.z; a.w += v.w;
        }
        const int o = q * 64 + c * 4;
        const float4 bb = *(const float4*)(b3 + o);
        const float m = (sm.swf[row] >= 0) ? 1.0f : 0.0f;
        float* dst = sm.gf + row * 256 + o;
        dst[0] = (a.x + bb.x) * m;
        dst[1] = (a.y + bb.y) * m;
        dst[2] = (a.z + bb.z) * m;
        dst[3] = (a.w + bb.w) * m;
    }
    __syncthreads();

    // ---- all-gather gf quarters via DSMEM (3 peers x 4 rows x 16 groups) ----
    cluster.sync();
    if (t < 192) {
        const int pid = t >> 6;                     // 0..2 peer slot
        const int qp  = pid + (pid >= q ? 1 : 0);   // actual peer rank
        const int idx = t & 63;
        const int row = idx >> 4, c = idx & 15;
        const float* peer = cluster.map_shared_rank((const float*)sm.gf, qp);
        const int o = row * 256 + qp * 64 + c * 4;
        *(float4*)(sm.gf + o) = *(const float4*)(peer + o);
    }
    __syncthreads();

    // ---- ts quarter: relu(gf @ Wn1[:,quarter] + bn1), 4 rows (Wn1/4 = 64 KB) ----
    {
        const float4* W = (const float4*)Wn1;       // [256][64]
        const int c  = t & 15;
        const int ch = t >> 4;                      // 16 chunks x 16 k
        float4 a0 = {0,0,0,0}, a1 = {0,0,0,0}, a2 = {0,0,0,0}, a3 = {0,0,0,0};
        #pragma unroll
        for (int j = 0; j < 16; j++) {
            const int k = ch * 16 + j;
            const float4 wv = W[k * 64 + q * 16 + c];
            const float x0 = sm.gf[k], x1 = sm.gf[256 + k], x2 = sm.gf[512 + k], x3 = sm.gf[768 + k];
            a0.x = fmaf(x0, wv.x, a0.x); a0.y = fmaf(x0, wv.y, a0.y); a0.z = fmaf(x0, wv.z, a0.z); a0.w = fmaf(x0, wv.w, a0.w);
            a1.x = fmaf(x1, wv.x, a1.x); a1.y = fmaf(x1, wv.y, a1.y); a1.z = fmaf(x1, wv.z, a1.z); a1.w = fmaf(x1, wv.w, a1.w);
            a2.x = fmaf(x2, wv.x, a2.x); a2.y = fmaf(x2, wv.y, a2.y); a2.z = fmaf(x2, wv.z, a2.z); a2.w = fmaf(x2, wv.w, a2.w);
            a3.x = fmaf(x3, wv.x, a3.x); a3.y = fmaf(x3, wv.y, a3.y); a3.z = fmaf(x3, wv.z, a3.z); a3.w = fmaf(x3, wv.w, a3.w);
        }
        sm.sp4[0 * 256 + ch * 16 + c] = a0;
        sm.sp4[1 * 256 + ch * 16 + c] = a1;
        sm.sp4[2 * 256 + ch * 16 + c] = a2;
        sm.sp4[3 * 256 + ch * 16 + c] = a3;
    }
    __syncthreads();
    if (t < 64) {
        const int row = t >> 4, c = t & 15;
        float4 a = sm.sp4[row * 256 + c];
        #pragma unroll
        for (int s = 1; s < 16; s++) {
            const float4 v = sm.sp4[row * 256 + s * 16 + c];
            a.x += v.x; a.y += v.y; a.z += v.z; a.w += v.w;
        }
        const int o = q * 64 + c * 4;
        const float4 bb = *(const float4*)(bn1 + o);
        float* dst = sm.ts + row * 256 + o;
        dst[0] = fmaxf(a.x + bb.x, 0.0f);
        dst[1] = fmaxf(a.y + bb.y, 0.0f);
        dst[2] = fmaxf(a.z + bb.z, 0.0f);
        dst[3] = fmaxf(a.w + bb.w, 0.0f);
    }
    __syncthreads();

    // ---- all-gather ts quarters via DSMEM ----
    cluster.sync();
    if (t < 192) {
        const int pid = t >> 6;
        const int qp  = pid + (pid >= q ? 1 : 0);
        const int idx = t & 63;
        const int row = idx >> 4, c = idx & 15;
        const float* peer = cluster.map_shared_rank((const float*)sm.ts, qp);
        const int o = row * 256 + qp * 64 + c * 4;
        *(float4*)(sm.ts + o) = *(const float4*)(peer + o);
    }
    __syncthreads();

    // ---- y quarter: ts @ Wn2[:,quarter] + bn2 -> g_y, 4 rows (Wn2/4 = 64 KB) ----
    {
        const float4* W = (const float4*)Wn2;
        const int c  = t & 15;
        const int ch = t >> 4;
        float4 a0 = {0,0,0,0}, a1 = {0,0,0,0}, a2 = {0,0,0,0}, a3 = {0,0,0,0};
        #pragma unroll
        for (int j = 0; j < 16; j++) {
            const int k = ch * 16 + j;
            const float4 wv = W[k * 64 + q * 16 + c];
            const float x0 = sm.ts[k], x1 = sm.ts[256 + k], x2 = sm.ts[512 + k], x3 = sm.ts[768 + k];
            a0.x = fmaf(x0, wv.x, a0.x); a0.y = fmaf(x0, wv.y, a0.y); a0.z = fmaf(x0, wv.z, a0.z); a0.w = fmaf(x0, wv.w, a0.w);
            a1.x = fmaf(x1, wv.x, a1.x); a1.y = fmaf(x1, wv.y, a1.y); a1.z = fmaf(x1, wv.z, a1.z); a1.w = fmaf(x1, wv.w, a1.w);
            a2.x = fmaf(x2, wv.x, a2.x); a2.y = fmaf(x2, wv.y, a2.y); a2.z = fmaf(x2, wv.z, a2.z); a2.w = fmaf(x2, wv.w, a2.w);
            a3.x = fmaf(x3, wv.x, a3.x); a3.y = fmaf(x3, wv.y, a3.y); a3.z = fmaf(x3, wv.z, a3.z); a3.w = fmaf(x3, wv.w, a3.w);
        }
        sm.sp4[0 * 256 + ch * 16 + c] = a0;
        sm.sp4[1 * 256 + ch * 16 + c] = a1;
        sm.sp4[2 * 256 + ch * 16 + c] = a2;
        sm.sp4[3 * 256 + ch * 16 + c] = a3;
    }
    __syncthreads();
    if (t < 64) {
        const int row = t >> 4, c = t & 15;
        float4 a = sm.sp4[row * 256 + c];
        #pragma unroll
        for (int s = 1; s < 16; s++) {
            const float4 v = sm.sp4[row * 256 + s * 16 + c];
            a.x += v.x; a.y += v.y; a.z += v.z; a.w += v.w;
        }
        const int o = q * 64 + c * 4;
        const float4 bb = *(const float4*)(bn2 + o);
        float4 v = make_float4(a.x + bb.x, a.y + bb.y, a.z + bb.z, a.w + bb.w);
        *(float4*)(g_y + (r_base + row) * 256 + o) = v;
    }

    gsync();

    // ================= Heads: blocks 0-3, head k = b (R6 tail) =================
    if (b < 4) {
        const int k = b;
        float* agg = sm.ts;                 // reuse as agg[256]
        float* pfl = (float*)sm.sp4;
        {   // agg = mean over 64 rows of g_y
            const float4* Y = (const float4*)g_y;   // [64][64]
            const int c  = t & 63;
            const int rc = t >> 6;
            float4 a = {0,0,0,0};
            #pragma unroll
            for (int j = 0; j < 16; j++) {
                const float4 v = Y[(rc * 16 + j) * 64 + c];
                a.x += v.x; a.y += v.y; a.z += v.z; a.w += v.w;
            }
            sm.sp4[rc * 64 + c] = a;
        }
        __syncthreads();
        agg[t] = (pfl[t] + pfl[256 + t] + pfl[512 + t] + pfl[768 + t]) * (1.0f / 64.0f);
        __syncthreads();

        {   // z = agg @ Wh1[k]: 32 float4 d-groups x 8 c-slices
            const int dg   = t & 31;
            const int half = t >> 5;
            const float* Wb = Wh1 + k * 32768 + dg * 4;
            float4 acc = {0,0,0,0};
            const int c0 = half * 32;
            #pragma unroll
            for (int c2 = c0; c2 < c0 + 32; c2++) {
                const float  av = agg[c2];
                const float4 wv = *(const float4*)(Wb + c2 * 128);
                acc.x = fmaf(av, wv.x, acc.x); acc.y = fmaf(av, wv.y, acc.y);
                acc.z = fmaf(av, wv.z, acc.z); acc.w = fmaf(av, wv.w, acc.w);
            }
            sm.sp4[t] = acc;
        }
        __syncthreads();
        if (t < 32) {
            float4 a = sm.sp4[t];
            #pragma unroll
            for (int s = 1; s < 8; s++) {
                const float4 v = sm.sp4[t + 32 * s];
                a.x += v.x; a.y += v.y; a.z += v.z; a.w += v.w;
            }
            const int o = t * 4;
            sm.h1s[o + 0] = fmaxf(a.x + bh1[k * 128 + o + 0], 0.0f);
            sm.h1s[o + 1] = fmaxf(a.y + bh1[k * 128 + o + 1], 0.0f);
            sm.h1s[o + 2] = fmaxf(a.z + bh1[k * 128 + o + 2], 0.0f);
            sm.h1s[o + 3] = fmaxf(a.w + bh1[k * 128 + o + 3], 0.0f);
        }
        __syncthreads();
        if (t < 32) {
            float a = 0.0f;
            #pragma unroll
            for (int j = t; j < 128; j += 32)
                a = fmaf(sm.h1s[j], Wh2[k * 128 + j], a);
            #pragma unroll
            for (int off = 16; off; off >>= 1)
                a += __shfl_xor_sync(0xffffffffu, a, off);
            if (t == 0) out[k] = a + bh2[k];
        }
    }
}

extern "C" void kernel_launch(void* const* d_in, const int* in_sizes, int n_in,
                              void* d_out, int out_size)
{
    const float* positions = (const float*)d_in[0];
    const float* grid_pts  = (const float*)d_in[1];
    const float* W1  = (const float*)d_in[2];
    const float* b1  = (const float*)d_in[3];
    const float* W2  = (const float*)d_in[4];
    const float* b2  = (const float*)d_in[5];
    const float* W3  = (const float*)d_in[6];
    const float* b3  = (const float*)d_in[7];
    const float* Wn1 = (const float*)d_in[8];
    const float* bn1 = (const float*)d_in[9];
    const float* Wn2 = (const float*)d_in[10];
    const float* bn2 = (const float*)d_in[11];
    const float* Wh1 = (const float*)d_in[12];
    const float* bh1 = (const float*)d_in[13];
    const float* Wh2 = (const float*)d_in[14];
    const float* bh2 = (const float*)d_in[15];
    float* out = (float*)d_out;

    fused_kernel<<<NB, 256>>>(positions, grid_pts, W1, b1, W2, b2, W3, b3,
                              Wn1, bn1, Wn2, bn2, Wh1, bh1, Wh2, bh2, out);
}

// round 12
// speedup vs baseline: 1.1746x; 1.1571x over previous
#include <cuda_runtime.h>
#include <cuda_bf16.h>
#include <cooperative_groups.h>

namespace cg = cooperative_groups;

// ---------------------------------------------------------------------------
// Fused persistent kernel: 128 blocks = 32 clusters of 4, ONE grid sync
// (arrive-only for blocks with no post-sync work).
// Only feat[0:64] is live (winner in -1..63) -> 500K-row MLP collapses to 64.
//
// Cluster cid = b>>2 owns rows r0=2*cid, r1=r0+1; rank q = b&3 owns
// column quarter [64q, 64q+64) of every 256-wide activation:
//   - winner table redundant; w0,w1 for the two rows
//   - MLP: L1,L2 redundant (cheap); L3 computes gf quarter (W3/4)
//   - all-gather gf quarters via DSMEM (cluster.sync)
//   - ts quarter = relu(gf @ Wn1[:,quarter] + bn1)   (Wn1/4)
//   - all-gather ts quarters via DSMEM (cluster.sync)
//   - y quarter = ts @ Wn2[:,quarter] + bn2 -> g_y   (Wn2/4)
// arrive (all 128); blocks 4-127 exit; blocks 0-3 wait then:
//   - agg = mean(g_y); head k=b -> out[k]
// ---------------------------------------------------------------------------

#define G   64
#define NB  128

__device__ float g_y[G * 256];
__device__ unsigned long long g_ctr;   // monotonic across launches/replays

struct SmemLayout {
    float  gf[2 * 256];     // full gf rows (own quarter + gathered)
    float  ts[2 * 256];     // full ts rows (reused as agg in heads)
    float4 sp4[512];        // chunk partials
    float  ps[192];
    float  gs[192];
    float  h1[2 * 64];
    float  h2[2 * 128];
    float  p[8];
    float  h1s[128];
    int    si[G];
    int    sw[4];
};

__global__ void __launch_bounds__(256, 1) __cluster_dims__(4, 1, 1)
fused_kernel(const float* __restrict__ pos, const float* __restrict__ gp,
             const float* __restrict__ W1,  const float* __restrict__ b1,
             const float* __restrict__ W2,  const float* __restrict__ b2,
             const float* __restrict__ W3,  const float* __restrict__ b3,
             const float* __restrict__ Wn1, const float* __restrict__ bn1,
             const float* __restrict__ Wn2, const float* __restrict__ bn2,
             const float* __restrict__ Wh1, const float* __restrict__ bh1,
             const float* __restrict__ Wh2, const float* __restrict__ bh2,
             float* __restrict__ out)
{
    __shared__ SmemLayout sm;
    const int b = blockIdx.x;
    const int t = threadIdx.x;
    cg::cluster_group cluster = cg::this_cluster();
    const int q   = b & 3;             // column quarter rank
    const int cid = b >> 2;            // cluster id
    const int r0  = cid * 2;
    const int r1  = r0 + 1;

    // ---- winner table (redundant per block) ----
    if (t < G * 3) { sm.ps[t] = pos[t]; sm.gs[t] = gp[t]; }
    __syncthreads();
    if (t < G) {
        const float px = sm.ps[t * 3], py = sm.ps[t * 3 + 1], pz = sm.ps[t * 3 + 2];
        float best = 3.4e38f; int bj = 0;
        #pragma unroll 4
        for (int j = 0; j < G; j++) {
            float dx = px - sm.gs[j * 3];
            float dy = py - sm.gs[j * 3 + 1];
            float dz = pz - sm.gs[j * 3 + 2];
            float d  = dx * dx + dy * dy + dz * dz;
            if (d < best) { best = d; bj = j; }     // argmin: first idx on ties
        }
        sm.si[t] = bj;
    }
    __syncthreads();
    if (t < G) {
        int c0 = (sm.si[t] == r0) ? t : -1;
        int c1 = (sm.si[t] == r1) ? t : -1;
        #pragma unroll
        for (int off = 16; off; off >>= 1) {
            c0 = max(c0, __shfl_xor_sync(0xffffffffu, c0, off));
            c1 = max(c1, __shfl_xor_sync(0xffffffffu, c1, off));
        }
        if ((t & 31) == 0) { sm.sw[t >> 5] = c0; sm.sw[2 + (t >> 5)] = c1; }
    }
    __syncthreads();
    const int w0 = max(sm.sw[0], sm.sw[1]);
    const int w1 = max(sm.sw[2], sm.sw[3]);

    // ---- MLP for both rows (clip(winner,0); zero-mask at gf) ----
    float* pf = (float*)sm.sp4;
    if (t < 3) {
        sm.p[t]     = pos[max(w0, 0) * 3 + t];
        sm.p[4 + t] = pos[max(w1, 0) * 3 + t];
    }
    __syncthreads();
    if (t < 64) {       // layer1: 3 -> 64, both rows
        float wa = W1[t], wb = W1[64 + t], wc = W1[128 + t], bb = b1[t];
        sm.h1[t]      = fmaxf(bb + sm.p[0] * wa + sm.p[1] * wb + sm.p[2] * wc, 0.0f);
        sm.h1[64 + t] = fmaxf(bb + sm.p[4] * wa + sm.p[5] * wb + sm.p[6] * wc, 0.0f);
    }
    __syncthreads();
    {   // layer2: 64 -> 128, both rows; 32 float4 col-groups, 8 chunks x 8 k
        const float4* W = (const float4*)W2;        // [64][32]
        const int c  = t & 31;
        const int ch = t >> 5;
        float4 a0 = {0,0,0,0}, a1 = {0,0,0,0};
        #pragma unroll
        for (int j = 0; j < 8; j++) {
            int k = ch * 8 + j;
            float4 wv = W[k * 32 + c];
            float  x0 = sm.h1[k], x1 = sm.h1[64 + k];
            a0.x = fmaf(x0, wv.x, a0.x); a0.y = fmaf(x0, wv.y, a0.y);
            a0.z = fmaf(x0, wv.z, a0.z); a0.w = fmaf(x0, wv.w, a0.w);
            a1.x = fmaf(x1, wv.x, a1.x); a1.y = fmaf(x1, wv.y, a1.y);
            a1.z = fmaf(x1, wv.z, a1.z); a1.w = fmaf(x1, wv.w, a1.w);
        }
        sm.sp4[ch * 32 + c]       = a0;
        sm.sp4[256 + ch * 32 + c] = a1;
    }
    __syncthreads();
    if (t < 64) {       // combine layer2: (row, col-group)
        const int row = t >> 5;
        const int c   = t & 31;
        float4 a = sm.sp4[row * 256 + c];
        #pragma unroll
        for (int s = 1; s < 8; s++) {
            float4 v = sm.sp4[row * 256 + s * 32 + c];
            a.x += v.x; a.y += v.y; a.z += v.z; a.w += v.w;
        }
        const int o = c * 4;
        float4 bb = *(const float4*)(b2 + o);
        float* dst = sm.h2 + row * 128 + o;
        dst[0] = fmaxf(a.x + bb.x, 0.0f);
        dst[1] = fmaxf(a.y + bb.y, 0.0f);
        dst[2] = fmaxf(a.z + bb.z, 0.0f);
        dst[3] = fmaxf(a.w + bb.w, 0.0f);
    }
    __syncthreads();
    {   // layer3 QUARTER: 64 cols of gf, both rows; 16 groups, 16 chunks x 8 k
        const float4* W = (const float4*)W3;        // [128][64]
        const int c  = t & 15;
        const int ch = t >> 4;
        float4 a0 = {0,0,0,0}, a1 = {0,0,0,0};
        #pragma unroll
        for (int j = 0; j < 8; j++) {
            int k = ch * 8 + j;
            float4 wv = W[k * 64 + q * 16 + c];
            float  x0 = sm.h2[k], x1 = sm.h2[128 + k];
            a0.x = fmaf(x0, wv.x, a0.x); a0.y = fmaf(x0, wv.y, a0.y);
            a0.z = fmaf(x0, wv.z, a0.z); a0.w = fmaf(x0, wv.w, a0.w);
            a1.x = fmaf(x1, wv.x, a1.x); a1.y = fmaf(x1, wv.y, a1.y);
            a1.z = fmaf(x1, wv.z, a1.z); a1.w = fmaf(x1, wv.w, a1.w);
        }
        sm.sp4[ch * 16 + c]       = a0;
        sm.sp4[256 + ch * 16 + c] = a1;
    }
    __syncthreads();
    if (t < 32) {       // combine gf quarter
        const int row = t >> 4;
        const int c   = t & 15;
        float4 a = sm.sp4[row * 256 + c];
        #pragma unroll
        for (int s = 1; s < 16; s++) {
            float4 v = sm.sp4[row * 256 + s * 16 + c];
            a.x += v.x; a.y += v.y; a.z += v.z; a.w += v.w;
        }
        const int o = q * 64 + c * 4;
        float4 bb = *(const float4*)(b3 + o);
        const int wr = row ? w1 : w0;
        const float m = (wr >= 0) ? 1.0f : 0.0f;
        float* dst = sm.gf + row * 256 + o;
        dst[0] = (a.x + bb.x) * m;
        dst[1] = (a.y + bb.y) * m;
        dst[2] = (a.z + bb.z) * m;
        dst[3] = (a.w + bb.w) * m;
    }
    __syncthreads();

    // ---- all-gather gf quarters via DSMEM ----
    cluster.sync();
    if (t < 96) {
        const int pid = t >> 5;                     // 0..2 peer slot
        const int qp  = pid + (pid >= q ? 1 : 0);   // actual peer rank
        const int idx = t & 31;
        const int row = idx >> 4;
        const int c   = idx & 15;
        const float* peer_gf = cluster.map_shared_rank((const float*)sm.gf, qp);
        const int o = row * 256 + qp * 64 + c * 4;
        *(float4*)(sm.gf + o) = *(const float4*)(peer_gf + o);
    }
    __syncthreads();

    // ---- ts quarter: relu(gf @ Wn1[:,quarter] + bn1), both rows ----
    {
        const float4* W = (const float4*)Wn1;       // [256][64]
        const int c  = t & 15;
        const int ch = t >> 4;                      // 16 chunks x 16 k
        float4 a0 = {0,0,0,0}, a1 = {0,0,0,0};
        #pragma unroll
        for (int j = 0; j < 16; j++) {
            int k = ch * 16 + j;
            float4 wv = W[k * 64 + q * 16 + c];
            float  x0 = sm.gf[k], x1 = sm.gf[256 + k];
            a0.x = fmaf(x0, wv.x, a0.x); a0.y = fmaf(x0, wv.y, a0.y);
            a0.z = fmaf(x0, wv.z, a0.z); a0.w = fmaf(x0, wv.w, a0.w);
            a1.x = fmaf(x1, wv.x, a1.x); a1.y = fmaf(x1, wv.y, a1.y);
            a1.z = fmaf(x1, wv.z, a1.z); a1.w = fmaf(x1, wv.w, a1.w);
        }
        sm.sp4[ch * 16 + c]       = a0;
        sm.sp4[256 + ch * 16 + c] = a1;
    }
    __syncthreads();
    if (t < 32) {
        const int row = t >> 4;
        const int c   = t & 15;
        float4 a = sm.sp4[row * 256 + c];
        #pragma unroll
        for (int s = 1; s < 16; s++) {
            float4 v = sm.sp4[row * 256 + s * 16 + c];
            a.x += v.x; a.y += v.y; a.z += v.z; a.w += v.w;
        }
        const int o = q * 64 + c * 4;
        float4 bb = *(const float4*)(bn1 + o);
        float* dst = sm.ts + row * 256 + o;
        dst[0] = fmaxf(a.x + bb.x, 0.0f);
        dst[1] = fmaxf(a.y + bb.y, 0.0f);
        dst[2] = fmaxf(a.z + bb.z, 0.0f);
        dst[3] = fmaxf(a.w + bb.w, 0.0f);
    }
    __syncthreads();

    // ---- all-gather ts quarters via DSMEM ----
    cluster.sync();
    if (t < 96) {
        const int pid = t >> 5;
        const int qp  = pid + (pid >= q ? 1 : 0);
        const int idx = t & 31;
        const int row = idx >> 4;
        const int c   = idx & 15;
        const float* peer_ts = cluster.map_shared_rank((const float*)sm.ts, qp);
        const int o = row * 256 + qp * 64 + c * 4;
        *(float4*)(sm.ts + o) = *(const float4*)(peer_ts + o);
    }
    __syncthreads();

    // ---- y quarter: ts @ Wn2[:,quarter] + bn2 -> g_y, both rows ----
    {
        const float4* W = (const float4*)Wn2;
        const int c  = t & 15;
        const int ch = t >> 4;
        float4 a0 = {0,0,0,0}, a1 = {0,0,0,0};
        #pragma unroll
        for (int j = 0; j < 16; j++) {
            int k = ch * 16 + j;
            float4 wv = W[k * 64 + q * 16 + c];
            float  x0 = sm.ts[k], x1 = sm.ts[256 + k];
            a0.x = fmaf(x0, wv.x, a0.x); a0.y = fmaf(x0, wv.y, a0.y);
            a0.z = fmaf(x0, wv.z, a0.z); a0.w = fmaf(x0, wv.w, a0.w);
            a1.x = fmaf(x1, wv.x, a1.x); a1.y = fmaf(x1, wv.y, a1.y);
            a1.z = fmaf(x1, wv.z, a1.z); a1.w = fmaf(x1, wv.w, a1.w);
        }
        sm.sp4[ch * 16 + c]       = a0;
        sm.sp4[256 + ch * 16 + c] = a1;
    }
    __syncthreads();
    if (t < 32) {
        const int row = t >> 4;
        const int c   = t & 15;
        float4 a = sm.sp4[row * 256 + c];
        #pragma unroll
        for (int s = 1; s < 16; s++) {
            float4 v = sm.sp4[row * 256 + s * 16 + c];
            a.x += v.x; a.y += v.y; a.z += v.z; a.w += v.w;
        }
        const int o = q * 64 + c * 4;
        float4 bb = *(const float4*)(bn2 + o);
        const int r = row ? r1 : r0;
        float4 v = make_float4(a.x + bb.x, a.y + bb.y, a.z + bb.z, a.w + bb.w);
        *(float4*)(g_y + r * 256 + o) = v;
    }

    // ---- grid sync: all arrive; only blocks 0-3 wait ----
    __syncthreads();                    // g_y writes complete block-wide
    if (b >= 4) {
        if (t == 0) {
            __threadfence();            // publish g_y before arrival
            atomicAdd(&g_ctr, 1ULL);
        }
        return;                         // 124 blocks retire immediately
    }
    if (t == 0) {
        __threadfence();
        unsigned long long ticket = atomicAdd(&g_ctr, 1ULL) + 1ULL;
        unsigned long long target = ((ticket + (NB - 1)) / NB) * (unsigned long long)NB;
        volatile unsigned long long* pctr = (volatile unsigned long long*)&g_ctr;
        while (*pctr < target) { }
        __threadfence();
    }
    __syncthreads();

    // ================= Heads: blocks 0-3, head k = b =================
    {
        const int k = b;
        float* agg = sm.ts;                 // reuse as agg[256]
        float* pfl = (float*)sm.sp4;
        {   // agg = mean over 64 rows of g_y
            const float4* Y = (const float4*)g_y;   // [64][64]
            const int c  = t & 63;
            const int rc = t >> 6;
            float4 a = {0,0,0,0};
            #pragma unroll
            for (int j = 0; j < 16; j++) {
                float4 v = Y[(rc * 16 + j) * 64 + c];
                a.x += v.x; a.y += v.y; a.z += v.z; a.w += v.w;
            }
            sm.sp4[rc * 64 + c] = a;
        }
        __syncthreads();
        agg[t] = (pfl[t] + pfl[256 + t] + pfl[512 + t] + pfl[768 + t]) * (1.0f / 64.0f);
        __syncthreads();

        {   // z = agg @ Wh1[k]: 32 float4 d-groups x 8 c-slices
            const int dg   = t & 31;
            const int half = t >> 5;
            const float* Wb = Wh1 + k * 32768 + dg * 4;
            float4 acc = {0,0,0,0};
            const int c0 = half * 32;
            #pragma unroll
            for (int c2 = c0; c2 < c0 + 32; c2++) {
                const float  av = agg[c2];
                const float4 wv = *(const float4*)(Wb + c2 * 128);
                acc.x = fmaf(av, wv.x, acc.x); acc.y = fmaf(av, wv.y, acc.y);
                acc.z = fmaf(av, wv.z, acc.z); acc.w = fmaf(av, wv.w, acc.w);
            }
            sm.sp4[t] = acc;
        }
        __syncthreads();
        if (t < 32) {
            float4 a = sm.sp4[t];
            #pragma unroll
            for (int s = 1; s < 8; s++) {
                const float4 v = sm.sp4[t + 32 * s];
                a.x += v.x; a.y += v.y; a.z += v.z; a.w += v.w;
            }
            const int o = t * 4;
            sm.h1s[o + 0] = fmaxf(a.x + bh1[k * 128 + o + 0], 0.0f);
            sm.h1s[o + 1] = fmaxf(a.y + bh1[k * 128 + o + 1], 0.0f);
            sm.h1s[o + 2] = fmaxf(a.z + bh1[k * 128 + o + 2], 0.0f);
            sm.h1s[o + 3] = fmaxf(a.w + bh1[k * 128 + o + 3], 0.0f);
        }
        __syncthreads();
        if (t < 32) {
            float a = 0.0f;
            #pragma unroll
            for (int j = t; j < 128; j += 32)
                a = fmaf(sm.h1s[j], Wh2[k * 128 + j], a);
            #pragma unroll
            for (int off = 16; off; off >>= 1)
                a += __shfl_xor_sync(0xffffffffu, a, off);
            if (t == 0) out[k] = a + bh2[k];
        }
    }
}

extern "C" void kernel_launch(void* const* d_in, const int* in_sizes, int n_in,
                              void* d_out, int out_size)
{
    const float* positions = (const float*)d_in[0];
    const float* grid_pts  = (const float*)d_in[1];
    const float* W1  = (const float*)d_in[2];
    const float* b1  = (const float*)d_in[3];
    const float* W2  = (const float*)d_in[4];
    const float* b2  = (const float*)d_in[5];
    const float* W3  = (const float*)d_in[6];
    const float* b3  = (const float*)d_in[7];
    const float* Wn1 = (const float*)d_in[8];
    const float* bn1 = (const float*)d_in[9];
    const float* Wn2 = (const float*)d_in[10];
    const float* bn2 = (const float*)d_in[11];
    const float* Wh1 = (const float*)d_in[12];
    const float* bh1 = (const float*)d_in[13];
    const float* Wh2 = (const float*)d_in[14];
    const float* bh2 = (const float*)d_in[15];
    float* out = (float*)d_out;

    fused_kernel<<<NB, 256>>>(positions, grid_pts, W1, b1, W2, b2, W3, b3,
                              Wn1, bn1, Wn2, bn2, Wh1, bh1, Wh2, bh2, out);
}